// round 5
// baseline (speedup 1.0000x reference)
#include <cuda_runtime.h>
#include <cstdint>
#include <cstddef>

#define Bb 512
#define Tt 2048
#define Cc 8
#define Mm 100
#define Nn 16
#define CM 800            // C*M
#define PITCH 20          // padded row length in floats (80B, conflict-free stride)

#define NTHREADS 512
#define NB 4              // batch elements per CTA
#define NSLOT 128
#define NWARP 16

// shared memory layout (float offsets)
#define SP_OFF   0                          // scaled S rows: 800*20
#define AP_OFF   (CM*PITCH)                 // A rows:        800*20
#define UR_OFF   (2*CM*PITCH)               // float2 {U, -L*||S||^2} : 800*2
#define PART_OFF (UR_OFF + 2*CM)            // warp partials: 16*4*16
#define SNEW_OFF (PART_OFF + NWARP*NB*Nn)   // new state: 4*16
#define GATE_OFF (SNEW_OFF + NB*Nn)         // gate double buffer: 2*4*8
#define XS_OFF   (GATE_OFF + 2*NB*Cc)       // x double buffer: 2*4
#define SMEM_FLOATS (XS_OFF + 2*NB)
#define SMEM_BYTES (SMEM_FLOATS*4)

// gate scratch: [T][B][C] floats (33.5 MB, L2-resident during the recurrence)
__device__ float g_gate[(size_t)Tt * Bb * Cc];

// ---------- packed f32x2 helpers ----------
__device__ __forceinline__ unsigned long long pk2(float lo, float hi) {
    unsigned long long r;
    asm("mov.b64 %0, {%1, %2};" : "=l"(r) : "f"(lo), "f"(hi));
    return r;
}
__device__ __forceinline__ void upk2(unsigned long long v, float& lo, float& hi) {
    asm("mov.b64 {%0, %1}, %2;" : "=f"(lo), "=f"(hi) : "l"(v));
}
__device__ __forceinline__ unsigned long long ffma2(unsigned long long a,
                                                    unsigned long long b,
                                                    unsigned long long c) {
    unsigned long long d;
    asm("fma.rn.f32x2 %0, %1, %2, %3;" : "=l"(d) : "l"(a), "l"(b), "l"(c));
    return d;
}
__device__ __forceinline__ unsigned long long fadd2(unsigned long long a,
                                                    unsigned long long b) {
    unsigned long long d;
    asm("add.rn.f32x2 %0, %1, %2;" : "=l"(d) : "l"(a), "l"(b));
    return d;
}
__device__ __forceinline__ float ex2f(float a) {
    float r;
    asm("ex2.approx.f32 %0, %1;" : "=f"(r) : "f"(a));
    return r;
}

// ---------- gate precompute: softmax(relu(x*W1+b1) @ W2 + b2) for all (b,t) ----------
__global__ void gate_precompute_kernel(const float* __restrict__ x,
                                       const float* __restrict__ W1,
                                       const float* __restrict__ b1,
                                       const float* __restrict__ W2,
                                       const float* __restrict__ b2) {
    int item = blockIdx.x * blockDim.x + threadIdx.x;
    if (item >= Bb * Tt) return;
    int t = item >> 9;      // / 512
    int b = item & (Bb - 1);
    float xv = x[(size_t)b * Tt + t];

    float h[16];
#pragma unroll
    for (int j = 0; j < 16; j++)
        h[j] = fmaxf(fmaf(xv, __ldg(W1 + j), __ldg(b1 + j)), 0.0f);

    float lg[8];
#pragma unroll
    for (int c = 0; c < 8; c++) {
        float s = __ldg(b2 + c);
#pragma unroll
        for (int j = 0; j < 16; j++)
            s = fmaf(h[j], __ldg(W2 + j * 8 + c), s);
        lg[c] = s;
    }
    float mx = lg[0];
#pragma unroll
    for (int c = 1; c < 8; c++) mx = fmaxf(mx, lg[c]);
    float sum = 0.0f;
#pragma unroll
    for (int c = 0; c < 8; c++) { lg[c] = __expf(lg[c] - mx); sum += lg[c]; }
    float inv = __fdividef(1.0f, sum);
#pragma unroll
    for (int c = 0; c < 8; c++)
        g_gate[(size_t)item * Cc + c] = lg[c] * inv;
}

// ---------- main persistent recurrent kernel ----------
// 128 CTAs x 512 threads; CTA owns 4 batch elements for all T steps.
// Lane mapping: b = tid&3, slot = tid>>2 (slot strides cm by 128).
__global__ void __launch_bounds__(NTHREADS, 1)
kaarma_kernel(const float* __restrict__ x,
              const float* __restrict__ S,
              const float* __restrict__ U,
              const float* __restrict__ A,
              float* __restrict__ out) {
    extern __shared__ float sh[];
    const int tid = threadIdx.x;
    const int b = tid & 3;          // batch element within CTA
    const int slot = tid >> 2;      // cm slot 0..127
    const int b_base = blockIdx.x * NB;
    const int wid = tid >> 5;
    const int lane = tid & 31;
    const float L2E = 1.4426950408889634f;
    const float NEGL = -L2E;

    // ---- prologue: build scaled S, A, {U, -L*||S||^2} tables in smem ----
    for (int r = tid; r < CM; r += NTHREADS) {
        const float* srow = S + r * Nn;
        const float* arow = A + r * Nn;
        float ss = 0.0f;
#pragma unroll
        for (int n = 0; n < Nn; n++) {
            float v = srow[n];
            ss = fmaf(v, v, ss);
            sh[SP_OFF + r * PITCH + n] = (2.0f * L2E) * v;
            sh[AP_OFF + r * PITCH + n] = arow[n];
        }
        float2* urp = (float2*)(sh + UR_OFF);
        urp[r] = make_float2(U[r], NEGL * ss);
    }
    // gate / x for t = 0
    if (tid < 32) {
        sh[GATE_OFF + tid] =
            g_gate[((size_t)0 * Bb + b_base + (tid >> 3)) * Cc + (tid & 7)];
    } else if (tid < 36) {
        sh[XS_OFF + (tid - 32)] = x[(size_t)(b_base + tid - 32) * Tt + 0];
    }
    __syncthreads();

    unsigned long long st[8];
#pragma unroll
    for (int k = 0; k < 8; k++) st[k] = 0ull;

    const ulonglong2* spv = (const ulonglong2*)(sh + SP_OFF);
    const ulonglong2* apv = (const ulonglong2*)(sh + AP_OFF);
    const float2* urv = (const float2*)(sh + UR_OFF);
    const bool wrlane = (lane < 4);

    for (int t = 0; t < Tt; t++) {
        const int par = t & 1;

        // prefetch next-step gate / x from global (L2-resident), stash later
        float gpref = 0.0f, xpref = 0.0f;
        {
            int tn = (t + 1 < Tt) ? (t + 1) : (Tt - 1);
            if (tid < 32)
                gpref = g_gate[((size_t)tn * Bb + b_base + (tid >> 3)) * Cc + (tid & 7)];
            else if (tid < 36)
                xpref = x[(size_t)(b_base + tid - 32) * Tt + tn];
        }

        // -L * ||state||^2  (shared by every cm this thread evaluates)
        unsigned long long q = 0ull;
#pragma unroll
        for (int k = 0; k < 8; k++) q = ffma2(st[k], st[k], q);
        float ql, qh; upk2(q, ql, qh);
        const float negsn = NEGL * (ql + qh);
        const float xv = sh[XS_OFF + par * NB + b];
        const float* gbase = sh + GATE_OFF + par * (NB * Cc) + b * Cc;

        unsigned long long acc[8];
#pragma unroll
        for (int k = 0; k < 8; k++) acc[k] = 0ull;

        // phi = ex2( -L||s||^2 - L||S||^2 + 2L s.S - L (x-U)^2 ) = exp(-dist - du^2)
#define CM_BODY(CMI)                                                            \
        {                                                                       \
            const int cm_ = (CMI);                                              \
            const ulonglong2* sr_ = spv + cm_ * (PITCH / 4);                    \
            ulonglong2 p0_ = sr_[0], p1_ = sr_[1], p2_ = sr_[2], p3_ = sr_[3];  \
            float2 ur_ = urv[cm_];                                              \
            int c_ = (cm_ * 41) >> 12;  /* cm/100 for cm<800 */                 \
            float g_ = gbase[c_];                                               \
            unsigned long long d_ = pk2(negsn, ur_.y);                          \
            d_ = ffma2(st[0], p0_.x, d_);                                       \
            d_ = ffma2(st[1], p0_.y, d_);                                       \
            d_ = ffma2(st[2], p1_.x, d_);                                       \
            d_ = ffma2(st[3], p1_.y, d_);                                       \
            unsigned long long e_ = ffma2(st[4], p2_.x, 0ull);                  \
            e_ = ffma2(st[5], p2_.y, e_);                                       \
            e_ = ffma2(st[6], p3_.x, e_);                                       \
            e_ = ffma2(st[7], p3_.y, e_);                                       \
            d_ = fadd2(d_, e_);                                                 \
            float dl_, dh_; upk2(d_, dl_, dh_);                                 \
            float tm_ = xv - ur_.x;                                             \
            float arg_ = fmaf(NEGL * tm_, tm_, dl_ + dh_);                      \
            float w_ = ex2f(arg_) * g_;                                         \
            unsigned long long w2_ = pk2(w_, w_);                               \
            const ulonglong2* ar_ = apv + cm_ * (PITCH / 4);                    \
            ulonglong2 a0_ = ar_[0], a1_ = ar_[1], a2_ = ar_[2], a3_ = ar_[3];  \
            acc[0] = ffma2(w2_, a0_.x, acc[0]);                                 \
            acc[1] = ffma2(w2_, a0_.y, acc[1]);                                 \
            acc[2] = ffma2(w2_, a1_.x, acc[2]);                                 \
            acc[3] = ffma2(w2_, a1_.y, acc[3]);                                 \
            acc[4] = ffma2(w2_, a2_.x, acc[4]);                                 \
            acc[5] = ffma2(w2_, a2_.y, acc[5]);                                 \
            acc[6] = ffma2(w2_, a3_.x, acc[6]);                                 \
            acc[7] = ffma2(w2_, a3_.y, acc[7]);                                 \
        }

#pragma unroll 3
        for (int j = 0; j < 6; j++) {
            CM_BODY(slot + 128 * j);
        }
        if (slot < 32) {          // warp-uniform tail (warps 0-3 only)
            CM_BODY(768 + slot);
        }
#undef CM_BODY

        // ---- warp-level reduce across the 8 slot-lanes (same b: lanes 4 apart) ----
#pragma unroll
        for (int k = 0; k < 8; k++) {
            acc[k] = fadd2(acc[k], __shfl_down_sync(0xffffffffu, acc[k], 16));
            acc[k] = fadd2(acc[k], __shfl_down_sync(0xffffffffu, acc[k], 8));
            acc[k] = fadd2(acc[k], __shfl_down_sync(0xffffffffu, acc[k], 4));
        }
        if (wrlane) {
            ulonglong2* pw =
                (ulonglong2*)(sh + PART_OFF + wid * (NB * Nn) + b * Nn);
            pw[0] = make_ulonglong2(acc[0], acc[1]);
            pw[1] = make_ulonglong2(acc[2], acc[3]);
            pw[2] = make_ulonglong2(acc[4], acc[5]);
            pw[3] = make_ulonglong2(acc[6], acc[7]);
        }
        // stash prefetched gate/x for next step (other parity buffer)
        if (tid < 32)
            sh[GATE_OFF + (par ^ 1) * (NB * Cc) + tid] = gpref;
        else if (tid < 36)
            sh[XS_OFF + (par ^ 1) * NB + (tid - 32)] = xpref;

        __syncthreads();   // partials + next gate/x visible

        // ---- stage2: 64 leaders (b,n) sum the 16 warp partials ----
        if (tid < 64) {
            int lb = tid >> 4, ln = tid & 15;
            float v0 = 0.f, v1 = 0.f, v2 = 0.f, v3 = 0.f;
#pragma unroll
            for (int w = 0; w < 16; w += 4) {
                v0 += sh[PART_OFF + (w + 0) * 64 + lb * 16 + ln];
                v1 += sh[PART_OFF + (w + 1) * 64 + lb * 16 + ln];
                v2 += sh[PART_OFF + (w + 2) * 64 + lb * 16 + ln];
                v3 += sh[PART_OFF + (w + 3) * 64 + lb * 16 + ln];
            }
            float v = (v0 + v1) + (v2 + v3);
            sh[SNEW_OFF + lb * 16 + ln] = v;
            if (ln == 15)
                out[(size_t)(b_base + lb) * Tt + t] = v;   // state[:, -1]
        }
        __syncthreads();   // new state visible

        // reload state registers
        {
            const ulonglong2* sv = (const ulonglong2*)(sh + SNEW_OFF + b * Nn);
            ulonglong2 s0 = sv[0], s1 = sv[1], s2 = sv[2], s3 = sv[3];
            st[0] = s0.x; st[1] = s0.y; st[2] = s1.x; st[3] = s1.y;
            st[4] = s2.x; st[5] = s2.y; st[6] = s3.x; st[7] = s3.y;
        }
    }
}

extern "C" void kernel_launch(void* const* d_in, const int* in_sizes, int n_in,
                              void* d_out, int out_size) {
    const float* x  = (const float*)d_in[0];
    const float* S  = (const float*)d_in[1];
    const float* U  = (const float*)d_in[2];
    const float* A  = (const float*)d_in[3];
    const float* W1 = (const float*)d_in[4];
    const float* b1 = (const float*)d_in[5];
    const float* W2 = (const float*)d_in[6];
    const float* b2 = (const float*)d_in[7];
    float* out = (float*)d_out;

    (void)in_sizes; (void)n_in; (void)out_size;

    // Idempotent module-state change; first (uncaptured) correctness call
    // sets it before graph capture ever happens.
    cudaFuncSetAttribute(kaarma_kernel,
                         cudaFuncAttributeMaxDynamicSharedMemorySize,
                         SMEM_BYTES);

    gate_precompute_kernel<<<(Bb * Tt + 255) / 256, 256>>>(x, W1, b1, W2, b2);
    kaarma_kernel<<<Bb / NB, NTHREADS, SMEM_BYTES>>>(x, S, U, A, out);
}

// round 8
// speedup vs baseline: 1.2155x; 1.2155x over previous
#include <cuda_runtime.h>
#include <cstdint>
#include <cstddef>

#define Bb 512
#define Tt 2048
#define Cc 8
#define Nn 16
#define CM 800

#define NTHREADS 512
#define NB 4
#define NWARP 16

// smem layout (float offsets)
#define A_OFF    0                      // A rows [800][16]
#define UR_OFF   (CM*Nn)                // float2 {U, -L*||S||^2}: 800*2
#define PART_OFF (UR_OFF + 2*CM)        // partials: 16 wid * 2 sg * 4 b * 16 n = 2048
#define SNEW_OFF (PART_OFF + NWARP*2*NB*Nn)
#define GATE_OFF (SNEW_OFF + NB*Nn)     // 2 par * 4 b * 8 c
#define XS_OFF   (GATE_OFF + 2*NB*Cc)   // 2 par * 4
#define SMEM_FLOATS (XS_OFF + 2*NB)
#define SMEM_BYTES (SMEM_FLOATS*4)

__device__ float g_gate[(size_t)Tt * Bb * Cc];

typedef unsigned long long u64;

__device__ __forceinline__ u64 pk2(float lo, float hi) {
    u64 r; asm("mov.b64 %0, {%1, %2};" : "=l"(r) : "f"(lo), "f"(hi)); return r;
}
__device__ __forceinline__ void upk2(u64 v, float& lo, float& hi) {
    asm("mov.b64 {%0, %1}, %2;" : "=f"(lo), "=f"(hi) : "l"(v));
}
__device__ __forceinline__ u64 ffma2(u64 a, u64 b, u64 c) {
    u64 d; asm("fma.rn.f32x2 %0, %1, %2, %3;" : "=l"(d) : "l"(a), "l"(b), "l"(c)); return d;
}
__device__ __forceinline__ u64 fadd2(u64 a, u64 b) {
    u64 d; asm("add.rn.f32x2 %0, %1, %2;" : "=l"(d) : "l"(a), "l"(b)); return d;
}
__device__ __forceinline__ float ex2f(float a) {
    float r; asm("ex2.approx.f32 %0, %1;" : "=f"(r) : "f"(a)); return r;
}
__device__ __forceinline__ float hsum2(u64 v) {
    float lo, hi; upk2(v, lo, hi); return lo + hi;
}
__device__ __forceinline__ u64 shfl_down64(u64 v, int d) {
    float lo, hi; upk2(v, lo, hi);
    lo = __shfl_down_sync(0xffffffffu, lo, d);
    hi = __shfl_down_sync(0xffffffffu, hi, d);
    return pk2(lo, hi);
}

// ---------- gate precompute ----------
__global__ void gate_precompute_kernel(const float* __restrict__ x,
                                       const float* __restrict__ W1,
                                       const float* __restrict__ b1,
                                       const float* __restrict__ W2,
                                       const float* __restrict__ b2) {
    int item = blockIdx.x * blockDim.x + threadIdx.x;
    if (item >= Bb * Tt) return;
    int t = item >> 9;
    int b = item & (Bb - 1);
    float xv = x[(size_t)b * Tt + t];

    float h[16];
#pragma unroll
    for (int j = 0; j < 16; j++)
        h[j] = fmaxf(fmaf(xv, __ldg(W1 + j), __ldg(b1 + j)), 0.0f);

    float lg[8];
#pragma unroll
    for (int c = 0; c < 8; c++) {
        float s = __ldg(b2 + c);
#pragma unroll
        for (int j = 0; j < 16; j++)
            s = fmaf(h[j], __ldg(W2 + j * 8 + c), s);
        lg[c] = s;
    }
    float mx = lg[0];
#pragma unroll
    for (int c = 1; c < 8; c++) mx = fmaxf(mx, lg[c]);
    float sum = 0.0f;
#pragma unroll
    for (int c = 0; c < 8; c++) { lg[c] = __expf(lg[c] - mx); sum += lg[c]; }
    float inv = __fdividef(1.0f, sum);
#pragma unroll
    for (int c = 0; c < 8; c++)
        g_gate[(size_t)item * Cc + c] = lg[c] * inv;
}

// ---------- main persistent kernel ----------
// lane role: q = tid&3 (N-quarter AND "own batch" = b_base+q for exp),
//            slot = tid>>2 (cm = slot + 128*j).
// Register slot k (0..3) refers to batch q^k (XOR-permuted, all static).
__global__ void __launch_bounds__(NTHREADS, 1)
kaarma_kernel(const float* __restrict__ x,
              const float* __restrict__ S,
              const float* __restrict__ U,
              const float* __restrict__ A,
              float* __restrict__ out) {
    extern __shared__ float sh[];
    const int tid = threadIdx.x;
    const int q = tid & 3;
    const int slot = tid >> 2;
    const int b_base = blockIdx.x * NB;
    const int wid = tid >> 5;
    const int lane = tid & 31;
    const float L2E = 1.4426950408889634f;
    const float NEGL = -L2E;

    // ---- prologue ----
    // A -> smem (plain [cm][16], lane-linear quarter reads later)
    {
        const float4* asrc = (const float4*)A;
        float4* adst = (float4*)(sh + A_OFF);
        for (int i = tid; i < CM * 4; i += NTHREADS) adst[i] = asrc[i];
    }
    // UR table {U, -L*||S||^2}
    for (int r = tid; r < CM; r += NTHREADS) {
        const float* srow = S + r * Nn;
        float ss = 0.0f;
#pragma unroll
        for (int n = 0; n < Nn; n++) { float v = srow[n]; ss = fmaf(v, v, ss); }
        ((float2*)(sh + UR_OFF))[r] = make_float2(U[r], NEGL * ss);
    }
    // S quarters -> registers, pre-scaled by 2*L2E
    u64 sreg[7][2];
#pragma unroll
    for (int j = 0; j < 6; j++) {
        float4 v = __ldg((const float4*)(S + (slot + 128 * j) * Nn + q * 4));
        sreg[j][0] = pk2(2.0f * L2E * v.x, 2.0f * L2E * v.y);
        sreg[j][1] = pk2(2.0f * L2E * v.z, 2.0f * L2E * v.w);
    }
    if (slot < 32) {
        float4 v = __ldg((const float4*)(S + (768 + slot) * Nn + q * 4));
        sreg[6][0] = pk2(2.0f * L2E * v.x, 2.0f * L2E * v.y);
        sreg[6][1] = pk2(2.0f * L2E * v.z, 2.0f * L2E * v.w);
    } else { sreg[6][0] = 0ull; sreg[6][1] = 0ull; }

    // gate / x for t = 0
    if (tid < 32) {
        sh[GATE_OFF + tid] =
            g_gate[((size_t)0 * Bb + b_base + (tid >> 3)) * Cc + (tid & 7)];
    } else if (tid < 36) {
        sh[XS_OFF + (tid - 32)] = x[(size_t)(b_base + tid - 32) * Tt + 0];
    }
    __syncthreads();

    // state quarters: sq[k] = state[batch q^k][4q..4q+3] as 2 f32x2
    u64 sq[4][2];
#pragma unroll
    for (int k = 0; k < 4; k++) { sq[k][0] = 0ull; sq[k][1] = 0ull; }

    const float* Asm = sh + A_OFF;
    const float2* urv = (const float2*)(sh + UR_OFF);

    for (int t = 0; t < Tt; t++) {
        const int par = t & 1;

        // prefetch next-step gate / x (L2-resident)
        float gpref = 0.0f, xpref = 0.0f;
        {
            int tn = (t + 1 < Tt) ? (t + 1) : (Tt - 1);
            if (tid < 32)
                gpref = g_gate[((size_t)tn * Bb + b_base + (tid >> 3)) * Cc + (tid & 7)];
            else if (tid < 36)
                xpref = x[(size_t)(b_base + tid - 32) * Tt + tn];
        }

        // -L * ||state_q||^2 (own batch only; partners compute theirs)
        float negsn0;
        {
            float p[4];
#pragma unroll
            for (int k = 0; k < 4; k++) {
                u64 tq = ffma2(sq[k][0], sq[k][0], 0ull);
                tq = ffma2(sq[k][1], sq[k][1], tq);
                p[k] = hsum2(tq);
            }
            float c0 = p[0] + __shfl_xor_sync(0xffffffffu, p[1], 1);
            float c2 = p[2] + __shfl_xor_sync(0xffffffffu, p[3], 1);
            float nrm = c0 + __shfl_xor_sync(0xffffffffu, c2, 2);
            negsn0 = NEGL * nrm;
        }
        const float xq = sh[XS_OFF + par * NB + q];
        const float* gbase = sh + GATE_OFF + par * (NB * Cc) + q * Cc;

        u64 acc[4][2];
#pragma unroll
        for (int k = 0; k < 4; k++) { acc[k][0] = 0ull; acc[k][1] = 0ull; }

#define CM_BODY(J, CMI)                                                         \
        {                                                                       \
            const int cm_ = (CMI);                                              \
            float2 ur_ = urv[cm_];                                              \
            int c_ = (cm_ * 41) >> 12;  /* cm/100 for cm<800 */                 \
            float g_ = gbase[c_];                                               \
            float pd[4];                                                        \
            _Pragma("unroll")                                                   \
            for (int k = 0; k < 4; k++) {                                       \
                u64 tq = ffma2(sq[k][0], sreg[J][0], 0ull);                     \
                tq = ffma2(sq[k][1], sreg[J][1], tq);                           \
                pd[k] = hsum2(tq);                                              \
            }                                                                   \
            float c0 = pd[0] + __shfl_xor_sync(0xffffffffu, pd[1], 1);          \
            float c2 = pd[2] + __shfl_xor_sync(0xffffffffu, pd[3], 1);          \
            float dot = c0 + __shfl_xor_sync(0xffffffffu, c2, 2);               \
            float du = xq - ur_.x;                                              \
            float arg = fmaf(NEGL * du, du, dot + negsn0 + ur_.y);              \
            float w0 = ex2f(arg) * g_;                                          \
            float w1 = __shfl_xor_sync(0xffffffffu, w0, 1);                     \
            float w2 = __shfl_xor_sync(0xffffffffu, w0, 2);                     \
            float w3 = __shfl_xor_sync(0xffffffffu, w1, 2);                     \
            ulonglong2 aq = *(const ulonglong2*)(Asm + cm_ * Nn + q * 4);       \
            u64 W;                                                              \
            W = pk2(w0, w0);                                                    \
            acc[0][0] = ffma2(W, aq.x, acc[0][0]);                              \
            acc[0][1] = ffma2(W, aq.y, acc[0][1]);                              \
            W = pk2(w1, w1);                                                    \
            acc[1][0] = ffma2(W, aq.x, acc[1][0]);                              \
            acc[1][1] = ffma2(W, aq.y, acc[1][1]);                              \
            W = pk2(w2, w2);                                                    \
            acc[2][0] = ffma2(W, aq.x, acc[2][0]);                              \
            acc[2][1] = ffma2(W, aq.y, acc[2][1]);                              \
            W = pk2(w3, w3);                                                    \
            acc[3][0] = ffma2(W, aq.x, acc[3][0]);                              \
            acc[3][1] = ffma2(W, aq.y, acc[3][1]);                              \
        }

        CM_BODY(0, slot)
        CM_BODY(1, slot + 128)
        CM_BODY(2, slot + 256)
        CM_BODY(3, slot + 384)
        CM_BODY(4, slot + 512)
        CM_BODY(5, slot + 640)
        if (slot < 32) {       // warp-uniform tail (warps 0-3)
            CM_BODY(6, 768 + slot)
        }
#undef CM_BODY

        // ---- reduce across slots within warp: 2 rounds (16, 8) ----
#pragma unroll
        for (int k = 0; k < 4; k++) {
            acc[k][0] = fadd2(acc[k][0], shfl_down64(acc[k][0], 16));
            acc[k][1] = fadd2(acc[k][1], shfl_down64(acc[k][1], 16));
            acc[k][0] = fadd2(acc[k][0], shfl_down64(acc[k][0], 8));
            acc[k][1] = fadd2(acc[k][1], shfl_down64(acc[k][1], 8));
        }
        if (lane < 8) {
            int sg = lane >> 2;   // 0 or 1
            float* base = sh + PART_OFF + ((wid * 2 + sg) * NB) * Nn;
#pragma unroll
            for (int k = 0; k < 4; k++) {
                *(ulonglong2*)(base + (q ^ k) * Nn + 4 * q) =
                    make_ulonglong2(acc[k][0], acc[k][1]);
            }
        }
        // stash prefetched gate/x for next step
        if (tid < 32)
            sh[GATE_OFF + (par ^ 1) * (NB * Cc) + tid] = gpref;
        else if (tid < 36)
            sh[XS_OFF + (par ^ 1) * NB + (tid - 32)] = xpref;

        __syncthreads();

        // ---- stage2: 64 leaders (b,n) sum 32 partials ----
        if (tid < 64) {
            int lb = tid >> 4, ln = tid & 15;
            float v0 = 0.f, v1 = 0.f, v2 = 0.f, v3 = 0.f;
#pragma unroll
            for (int w = 0; w < 32; w += 4) {
                v0 += sh[PART_OFF + ((w + 0) * NB + lb) * Nn + ln];
                v1 += sh[PART_OFF + ((w + 1) * NB + lb) * Nn + ln];
                v2 += sh[PART_OFF + ((w + 2) * NB + lb) * Nn + ln];
                v3 += sh[PART_OFF + ((w + 3) * NB + lb) * Nn + ln];
            }
            float v = (v0 + v1) + (v2 + v3);
            sh[SNEW_OFF + lb * Nn + ln] = v;
            if (ln == 15)
                out[(size_t)(b_base + lb) * Tt + t] = v;
        }
        __syncthreads();

        // reload state quarters: sq[k] = SNEW[q^k][4q..4q+3]
#pragma unroll
        for (int k = 0; k < 4; k++) {
            ulonglong2 v = *(const ulonglong2*)(sh + SNEW_OFF + (q ^ k) * Nn + 4 * q);
            sq[k][0] = v.x; sq[k][1] = v.y;
        }
    }
}

extern "C" void kernel_launch(void* const* d_in, const int* in_sizes, int n_in,
                              void* d_out, int out_size) {
    const float* x  = (const float*)d_in[0];
    const float* S  = (const float*)d_in[1];
    const float* U  = (const float*)d_in[2];
    const float* A  = (const float*)d_in[3];
    const float* W1 = (const float*)d_in[4];
    const float* b1 = (const float*)d_in[5];
    const float* W2 = (const float*)d_in[6];
    const float* b2 = (const float*)d_in[7];
    float* out = (float*)d_out;

    (void)in_sizes; (void)n_in; (void)out_size;

    cudaFuncSetAttribute(kaarma_kernel,
                         cudaFuncAttributeMaxDynamicSharedMemorySize,
                         SMEM_BYTES);

    gate_precompute_kernel<<<(Bb * Tt + 255) / 256, 256>>>(x, W1, b1, W2, b2);
    kaarma_kernel<<<Bb / NB, NTHREADS, SMEM_BYTES>>>(x, S, U, A, out);
}

// round 13
// speedup vs baseline: 1.2358x; 1.0167x over previous
#include <cuda_runtime.h>
#include <cstdint>
#include <cstddef>

#define Bb 512
#define Tt 2048
#define Cc 8
#define Nn 16
#define CM 800

#define NTHREADS 512
#define NB 4
#define NWARP 16

// smem layout (float offsets) — A now lives in registers
#define UR_OFF   0                        // float2 {U, -L*||S||^2}: 800*2
#define PART_OFF (2*CM)                   // partials: 64 sets * 4 b * 16 n = 4096
#define SNEW_OFF (PART_OFF + 64*NB*Nn)
#define GATE_OFF (SNEW_OFF + NB*Nn)       // 2 par * 4 b * 8 c
#define XS_OFF   (GATE_OFF + 2*NB*Cc)     // 2 par * 4
#define SMEM_FLOATS (XS_OFF + 2*NB)
#define SMEM_BYTES (SMEM_FLOATS*4)

__device__ float g_gate[(size_t)Tt * Bb * Cc];

typedef unsigned long long u64;

__device__ __forceinline__ u64 pk2(float lo, float hi) {
    u64 r; asm("mov.b64 %0, {%1, %2};" : "=l"(r) : "f"(lo), "f"(hi)); return r;
}
__device__ __forceinline__ void upk2(u64 v, float& lo, float& hi) {
    asm("mov.b64 {%0, %1}, %2;" : "=f"(lo), "=f"(hi) : "l"(v));
}
__device__ __forceinline__ u64 ffma2(u64 a, u64 b, u64 c) {
    u64 d; asm("fma.rn.f32x2 %0, %1, %2, %3;" : "=l"(d) : "l"(a), "l"(b), "l"(c)); return d;
}
__device__ __forceinline__ u64 fadd2(u64 a, u64 b) {
    u64 d; asm("add.rn.f32x2 %0, %1, %2;" : "=l"(d) : "l"(a), "l"(b)); return d;
}
__device__ __forceinline__ float ex2f(float a) {
    float r; asm("ex2.approx.f32 %0, %1;" : "=f"(r) : "f"(a)); return r;
}
__device__ __forceinline__ float hsum2(u64 v) {
    float lo, hi; upk2(v, lo, hi); return lo + hi;
}
__device__ __forceinline__ u64 shfl_down64(u64 v, int d) {
    float lo, hi; upk2(v, lo, hi);
    lo = __shfl_down_sync(0xffffffffu, lo, d);
    hi = __shfl_down_sync(0xffffffffu, hi, d);
    return pk2(lo, hi);
}

// ---------- gate precompute ----------
__global__ void gate_precompute_kernel(const float* __restrict__ x,
                                       const float* __restrict__ W1,
                                       const float* __restrict__ b1,
                                       const float* __restrict__ W2,
                                       const float* __restrict__ b2) {
    int item = blockIdx.x * blockDim.x + threadIdx.x;
    if (item >= Bb * Tt) return;
    int t = item >> 9;
    int b = item & (Bb - 1);
    float xv = x[(size_t)b * Tt + t];

    float h[16];
#pragma unroll
    for (int j = 0; j < 16; j++)
        h[j] = fmaxf(fmaf(xv, __ldg(W1 + j), __ldg(b1 + j)), 0.0f);

    float lg[8];
#pragma unroll
    for (int c = 0; c < 8; c++) {
        float s = __ldg(b2 + c);
#pragma unroll
        for (int j = 0; j < 16; j++)
            s = fmaf(h[j], __ldg(W2 + j * 8 + c), s);
        lg[c] = s;
    }
    float mx = lg[0];
#pragma unroll
    for (int c = 1; c < 8; c++) mx = fmaxf(mx, lg[c]);
    float sum = 0.0f;
#pragma unroll
    for (int c = 0; c < 8; c++) { lg[c] = __expf(lg[c] - mx); sum += lg[c]; }
    float inv = __fdividef(1.0f, sum);
#pragma unroll
    for (int c = 0; c < 8; c++)
        g_gate[(size_t)item * Cc + c] = lg[c] * inv;
}

// ---------- main persistent kernel ----------
// lane role: q = tid&3 (N-quarter AND own batch b_base+q), slot = tid>>2.
// Register slot k refers to batch q^k. S and A quarters live in registers.
__global__ void __launch_bounds__(NTHREADS, 1)
kaarma_kernel(const float* __restrict__ x,
              const float* __restrict__ S,
              const float* __restrict__ U,
              const float* __restrict__ A,
              float* __restrict__ out) {
    extern __shared__ float sh[];
    const int tid = threadIdx.x;
    const int q = tid & 3;
    const int slot = tid >> 2;
    const int b_base = blockIdx.x * NB;
    const int wid = tid >> 5;
    const int lane = tid & 31;
    const float L2E = 1.4426950408889634f;
    const float NEGL = -L2E;

    // ---- prologue ----
    // UR table {U, -L*||S||^2}
    for (int r = tid; r < CM; r += NTHREADS) {
        const float* srow = S + r * Nn;
        float ss = 0.0f;
#pragma unroll
        for (int n = 0; n < Nn; n++) { float v = srow[n]; ss = fmaf(v, v, ss); }
        ((float2*)(sh + UR_OFF))[r] = make_float2(U[r], NEGL * ss);
    }
    // S quarters (pre-scaled by 2*L2E) and A quarters -> registers
    u64 sreg[7][2], areg[7][2];
#pragma unroll
    for (int j = 0; j < 6; j++) {
        int cm = slot + 128 * j;
        float4 sv = __ldg((const float4*)(S + cm * Nn + q * 4));
        sreg[j][0] = pk2(2.0f * L2E * sv.x, 2.0f * L2E * sv.y);
        sreg[j][1] = pk2(2.0f * L2E * sv.z, 2.0f * L2E * sv.w);
        float4 av = __ldg((const float4*)(A + cm * Nn + q * 4));
        areg[j][0] = pk2(av.x, av.y);
        areg[j][1] = pk2(av.z, av.w);
    }
    if (slot < 32) {
        int cm = 768 + slot;
        float4 sv = __ldg((const float4*)(S + cm * Nn + q * 4));
        sreg[6][0] = pk2(2.0f * L2E * sv.x, 2.0f * L2E * sv.y);
        sreg[6][1] = pk2(2.0f * L2E * sv.z, 2.0f * L2E * sv.w);
        float4 av = __ldg((const float4*)(A + cm * Nn + q * 4));
        areg[6][0] = pk2(av.x, av.y);
        areg[6][1] = pk2(av.z, av.w);
    } else {
        sreg[6][0] = 0ull; sreg[6][1] = 0ull;
        areg[6][0] = 0ull; areg[6][1] = 0ull;
    }

    // gate / x for t = 0
    if (tid < 32) {
        sh[GATE_OFF + tid] =
            g_gate[((size_t)0 * Bb + b_base + (tid >> 3)) * Cc + (tid & 7)];
    } else if (tid < 36) {
        sh[XS_OFF + (tid - 32)] = x[(size_t)(b_base + tid - 32) * Tt + 0];
    }
    __syncthreads();

    // state quarters: sq[k] = state[batch q^k][4q..4q+3]
    u64 sq[4][2];
#pragma unroll
    for (int k = 0; k < 4; k++) { sq[k][0] = 0ull; sq[k][1] = 0ull; }

    const float2* urv = (const float2*)(sh + UR_OFF);

    for (int t = 0; t < Tt; t++) {
        const int par = t & 1;

        // prefetch next-step gate / x (L2-resident)
        float gpref = 0.0f, xpref = 0.0f;
        {
            int tn = (t + 1 < Tt) ? (t + 1) : (Tt - 1);
            if (tid < 32)
                gpref = g_gate[((size_t)tn * Bb + b_base + (tid >> 3)) * Cc + (tid & 7)];
            else if (tid < 36)
                xpref = x[(size_t)(b_base + tid - 32) * Tt + tn];
        }

        // -L * ||state_q||^2 (own batch)
        float negsn0;
        {
            float p[4];
#pragma unroll
            for (int k = 0; k < 4; k++) {
                u64 tq = ffma2(sq[k][0], sq[k][0], 0ull);
                tq = ffma2(sq[k][1], sq[k][1], tq);
                p[k] = hsum2(tq);
            }
            float c0 = p[0] + __shfl_xor_sync(0xffffffffu, p[1], 1);
            float c2 = p[2] + __shfl_xor_sync(0xffffffffu, p[3], 1);
            float nrm = c0 + __shfl_xor_sync(0xffffffffu, c2, 2);
            negsn0 = NEGL * nrm;
        }
        const float xq = sh[XS_OFF + par * NB + q];
        const float* gbase = sh + GATE_OFF + par * (NB * Cc) + q * Cc;

        u64 acc[4][2];
#pragma unroll
        for (int k = 0; k < 4; k++) { acc[k][0] = 0ull; acc[k][1] = 0ull; }

#define CM_BODY(J, CMI)                                                         \
        {                                                                       \
            const int cm_ = (CMI);                                              \
            float2 ur_ = urv[cm_];                                              \
            int c_ = (cm_ * 41) >> 12;  /* cm/100 for cm<800 */                 \
            float g_ = gbase[c_];                                               \
            float pd[4];                                                        \
            _Pragma("unroll")                                                   \
            for (int k = 0; k < 4; k++) {                                       \
                u64 tq = ffma2(sq[k][0], sreg[J][0], 0ull);                     \
                tq = ffma2(sq[k][1], sreg[J][1], tq);                           \
                pd[k] = hsum2(tq);                                              \
            }                                                                   \
            float c0 = pd[0] + __shfl_xor_sync(0xffffffffu, pd[1], 1);          \
            float c2 = pd[2] + __shfl_xor_sync(0xffffffffu, pd[3], 1);          \
            float dot = c0 + __shfl_xor_sync(0xffffffffu, c2, 2);               \
            float du = xq - ur_.x;                                              \
            float arg = fmaf(NEGL * du, du, dot + negsn0 + ur_.y);              \
            float w0 = ex2f(arg) * g_;                                          \
            float w1 = __shfl_xor_sync(0xffffffffu, w0, 1);                     \
            float w2 = __shfl_xor_sync(0xffffffffu, w0, 2);                     \
            float w3 = __shfl_xor_sync(0xffffffffu, w1, 2);                     \
            u64 W;                                                              \
            W = pk2(w0, w0);                                                    \
            acc[0][0] = ffma2(W, areg[J][0], acc[0][0]);                        \
            acc[0][1] = ffma2(W, areg[J][1], acc[0][1]);                        \
            W = pk2(w1, w1);                                                    \
            acc[1][0] = ffma2(W, areg[J][0], acc[1][0]);                        \
            acc[1][1] = ffma2(W, areg[J][1], acc[1][1]);                        \
            W = pk2(w2, w2);                                                    \
            acc[2][0] = ffma2(W, areg[J][0], acc[2][0]);                        \
            acc[2][1] = ffma2(W, areg[J][1], acc[2][1]);                        \
            W = pk2(w3, w3);                                                    \
            acc[3][0] = ffma2(W, areg[J][0], acc[3][0]);                        \
            acc[3][1] = ffma2(W, areg[J][1], acc[3][1]);                        \
        }

        CM_BODY(0, slot)
        CM_BODY(1, slot + 128)
        CM_BODY(2, slot + 256)
        CM_BODY(3, slot + 384)
        CM_BODY(4, slot + 512)
        CM_BODY(5, slot + 640)
        if (slot < 32) {       // warp-uniform tail (warps 0-3)
            CM_BODY(6, 768 + slot)
        }
#undef CM_BODY

        // ---- reduce: ONE shuffle round (down 16), then 16 lanes STS ----
#pragma unroll
        for (int k = 0; k < 4; k++) {
            acc[k][0] = fadd2(acc[k][0], shfl_down64(acc[k][0], 16));
            acc[k][1] = fadd2(acc[k][1], shfl_down64(acc[k][1], 16));
        }
        if (lane < 16) {
            int sgrp = lane >> 2;   // 0..3
            float* base = sh + PART_OFF + ((wid * 4 + sgrp) * NB) * Nn;
#pragma unroll
            for (int k = 0; k < 4; k++) {
                *(ulonglong2*)(base + (q ^ k) * Nn + 4 * q) =
                    make_ulonglong2(acc[k][0], acc[k][1]);
            }
        }
        // stash prefetched gate/x for next step
        if (tid < 32)
            sh[GATE_OFF + (par ^ 1) * (NB * Cc) + tid] = gpref;
        else if (tid < 36)
            sh[XS_OFF + (par ^ 1) * NB + (tid - 32)] = xpref;

        __syncthreads();

        // ---- stage2: 64 leaders (b,n) sum 64 partial sets ----
        if (tid < 64) {
            int lb = tid >> 4, ln = tid & 15;
            float v0 = 0.f, v1 = 0.f, v2 = 0.f, v3 = 0.f;
#pragma unroll
            for (int w = 0; w < 64; w += 4) {
                v0 += sh[PART_OFF + ((w + 0) * NB + lb) * Nn + ln];
                v1 += sh[PART_OFF + ((w + 1) * NB + lb) * Nn + ln];
                v2 += sh[PART_OFF + ((w + 2) * NB + lb) * Nn + ln];
                v3 += sh[PART_OFF + ((w + 3) * NB + lb) * Nn + ln];
            }
            float v = (v0 + v1) + (v2 + v3);
            sh[SNEW_OFF + lb * Nn + ln] = v;
            if (ln == 15)
                out[(size_t)(b_base + lb) * Tt + t] = v;
        }
        __syncthreads();

        // reload state quarters: sq[k] = SNEW[q^k][4q..4q+3]
#pragma unroll
        for (int k = 0; k < 4; k++) {
            ulonglong2 v = *(const ulonglong2*)(sh + SNEW_OFF + (q ^ k) * Nn + 4 * q);
            sq[k][0] = v.x; sq[k][1] = v.y;
        }
    }
}

extern "C" void kernel_launch(void* const* d_in, const int* in_sizes, int n_in,
                              void* d_out, int out_size) {
    const float* x  = (const float*)d_in[0];
    const float* S  = (const float*)d_in[1];
    const float* U  = (const float*)d_in[2];
    const float* A  = (const float*)d_in[3];
    const float* W1 = (const float*)d_in[4];
    const float* b1 = (const float*)d_in[5];
    const float* W2 = (const float*)d_in[6];
    const float* b2 = (const float*)d_in[7];
    float* out = (float*)d_out;

    (void)in_sizes; (void)n_in; (void)out_size;

    cudaFuncSetAttribute(kaarma_kernel,
                         cudaFuncAttributeMaxDynamicSharedMemorySize,
                         SMEM_BYTES);

    gate_precompute_kernel<<<(Bb * Tt + 255) / 256, 256>>>(x, W1, b1, W2, b2);
    kaarma_kernel<<<Bb / NB, NTHREADS, SMEM_BYTES>>>(x, S, U, A, out);
}